// round 2
// baseline (speedup 1.0000x reference)
#include <cuda_runtime.h>
#include <math.h>

// X [T=16384, H=2880] f32; W [E=128, H=2880] f32; bias [E=128] f32
// d_out (f32): [0,T*4) softmax top vals | [T*4,T*8) indices | [T*8,..) logits [T,E]
//
// Kernel 1: 128x128 fp32 SIMT GEMM + bias + logits store + top-5 scan.
//   Flags tokens whose top-5 adjacent gaps are < EPS (ambiguous ordering).
// Kernel 2: for flagged tokens, recompute logits with compensated (double-float)
//   accumulation and redo top-4 + softmax exactly.

#define BM 128
#define BN 128
#define BK 16
#define TM 8
#define TN 8
#define NTHREADS 256
#define LPAD 129
#define AMBIG_EPS 1e-4f

__device__ unsigned char g_flags[65536];

extern __shared__ float smem[];

__global__ __launch_bounds__(NTHREADS, 1)
void router_topk_kernel(const float* __restrict__ X,
                        const float* __restrict__ W,
                        const float* __restrict__ bias,
                        float* __restrict__ out_vals,
                        float* __restrict__ out_idx,
                        float* __restrict__ out_logits,
                        int T, int H)
{
    const int tid = threadIdx.x;
    const int tr  = tid >> 4;
    const int tc  = tid & 15;
    const int rowBase = blockIdx.x * BM;

    float* As = smem;             // [BK][BM]
    float* Bs = smem + BK * BM;   // [BK][BN]

    float acc[TM][TN];
    #pragma unroll
    for (int m = 0; m < TM; m++)
        #pragma unroll
        for (int n = 0; n < TN; n++) acc[m][n] = 0.0f;

    const int numTiles = H / BK;

    const int ar0 = tid >> 2,              ak0 = tid & 3;
    const int ar1 = (tid + NTHREADS) >> 2, ak1 = (tid + NTHREADS) & 3;

    float4 pa0, pa1, pb0, pb1;

    pa0 = *(const float4*)&X[(size_t)(rowBase + ar0) * H + ak0 * 4];
    pa1 = *(const float4*)&X[(size_t)(rowBase + ar1) * H + ak1 * 4];
    pb0 = *(const float4*)&W[(size_t)ar0 * H + ak0 * 4];
    pb1 = *(const float4*)&W[(size_t)ar1 * H + ak1 * 4];

    {
        As[(ak0 * 4 + 0) * BM + ar0] = pa0.x;
        As[(ak0 * 4 + 1) * BM + ar0] = pa0.y;
        As[(ak0 * 4 + 2) * BM + ar0] = pa0.z;
        As[(ak0 * 4 + 3) * BM + ar0] = pa0.w;
        As[(ak1 * 4 + 0) * BM + ar1] = pa1.x;
        As[(ak1 * 4 + 1) * BM + ar1] = pa1.y;
        As[(ak1 * 4 + 2) * BM + ar1] = pa1.z;
        As[(ak1 * 4 + 3) * BM + ar1] = pa1.w;
        Bs[(ak0 * 4 + 0) * BN + ar0] = pb0.x;
        Bs[(ak0 * 4 + 1) * BN + ar0] = pb0.y;
        Bs[(ak0 * 4 + 2) * BN + ar0] = pb0.z;
        Bs[(ak0 * 4 + 3) * BN + ar0] = pb0.w;
        Bs[(ak1 * 4 + 0) * BN + ar1] = pb1.x;
        Bs[(ak1 * 4 + 1) * BN + ar1] = pb1.y;
        Bs[(ak1 * 4 + 2) * BN + ar1] = pb1.z;
        Bs[(ak1 * 4 + 3) * BN + ar1] = pb1.w;
    }
    __syncthreads();

    for (int t = 0; t < numTiles; t++) {
        if (t + 1 < numTiles) {
            const int k0 = (t + 1) * BK;
            pa0 = *(const float4*)&X[(size_t)(rowBase + ar0) * H + k0 + ak0 * 4];
            pa1 = *(const float4*)&X[(size_t)(rowBase + ar1) * H + k0 + ak1 * 4];
            pb0 = *(const float4*)&W[(size_t)ar0 * H + k0 + ak0 * 4];
            pb1 = *(const float4*)&W[(size_t)ar1 * H + k0 + ak1 * 4];
        }

        #pragma unroll
        for (int k = 0; k < BK; k++) {
            float4 a0 = *(const float4*)&As[k * BM + tr * TM];
            float4 a1 = *(const float4*)&As[k * BM + tr * TM + 4];
            float4 b0 = *(const float4*)&Bs[k * BN + tc * TN];
            float4 b1 = *(const float4*)&Bs[k * BN + tc * TN + 4];
            float a[TM] = {a0.x, a0.y, a0.z, a0.w, a1.x, a1.y, a1.z, a1.w};
            float b[TN] = {b0.x, b0.y, b0.z, b0.w, b1.x, b1.y, b1.z, b1.w};
            #pragma unroll
            for (int m = 0; m < TM; m++)
                #pragma unroll
                for (int n = 0; n < TN; n++)
                    acc[m][n] = fmaf(a[m], b[n], acc[m][n]);
        }
        __syncthreads();

        if (t + 1 < numTiles) {
            As[(ak0 * 4 + 0) * BM + ar0] = pa0.x;
            As[(ak0 * 4 + 1) * BM + ar0] = pa0.y;
            As[(ak0 * 4 + 2) * BM + ar0] = pa0.z;
            As[(ak0 * 4 + 3) * BM + ar0] = pa0.w;
            As[(ak1 * 4 + 0) * BM + ar1] = pa1.x;
            As[(ak1 * 4 + 1) * BM + ar1] = pa1.y;
            As[(ak1 * 4 + 2) * BM + ar1] = pa1.z;
            As[(ak1 * 4 + 3) * BM + ar1] = pa1.w;
            Bs[(ak0 * 4 + 0) * BN + ar0] = pb0.x;
            Bs[(ak0 * 4 + 1) * BN + ar0] = pb0.y;
            Bs[(ak0 * 4 + 2) * BN + ar0] = pb0.z;
            Bs[(ak0 * 4 + 3) * BN + ar0] = pb0.w;
            Bs[(ak1 * 4 + 0) * BN + ar1] = pb1.x;
            Bs[(ak1 * 4 + 1) * BN + ar1] = pb1.y;
            Bs[(ak1 * 4 + 2) * BN + ar1] = pb1.z;
            Bs[(ak1 * 4 + 3) * BN + ar1] = pb1.w;
            __syncthreads();
        }
    }

    // ---------------- Epilogue ----------------
    float bb[TN];
    #pragma unroll
    for (int n = 0; n < TN; n++) bb[n] = bias[tc * TN + n];

    __syncthreads();
    float* Ls = smem; // [BM][LPAD]

    #pragma unroll
    for (int m = 0; m < TM; m++) {
        const int lrow  = tr * TM + m;
        const int token = rowBase + lrow;
        float v[TN];
        #pragma unroll
        for (int n = 0; n < TN; n++) v[n] = acc[m][n] + bb[n];

        float* lp = &Ls[lrow * LPAD + tc * TN];
        #pragma unroll
        for (int n = 0; n < TN; n++) lp[n] = v[n];

        if (token < T) {
            float4 o0 = make_float4(v[0], v[1], v[2], v[3]);
            float4 o1 = make_float4(v[4], v[5], v[6], v[7]);
            float* gp = &out_logits[(size_t)token * BN + tc * TN];
            *(float4*)gp       = o0;
            *(float4*)(gp + 4) = o1;
        }
    }
    __syncthreads();

    // top-5 scan (one thread per token); flag ambiguous tokens
    if (tid < BM) {
        const int token = rowBase + tid;
        if (token < T) {
            const float* row = &Ls[tid * LPAD];
            float tv[5] = {-1e30f, -1e30f, -1e30f, -1e30f, -1e30f};
            int   ti[5] = {0, 0, 0, 0, 0};
            for (int e = 0; e < BN; e++) {
                float val = row[e];
                if (val > tv[4]) {
                    tv[4] = val; ti[4] = e;
                    #pragma unroll
                    for (int s = 4; s > 0; s--) {
                        if (tv[s] > tv[s - 1]) {
                            float fv = tv[s]; tv[s] = tv[s - 1]; tv[s - 1] = fv;
                            int   fi = ti[s]; ti[s] = ti[s - 1]; ti[s - 1] = fi;
                        }
                    }
                }
            }
            // ambiguity: any adjacent gap among top-5 below EPS
            bool ambig = (tv[0] - tv[1] < AMBIG_EPS) |
                         (tv[1] - tv[2] < AMBIG_EPS) |
                         (tv[2] - tv[3] < AMBIG_EPS) |
                         (tv[3] - tv[4] < AMBIG_EPS);
            g_flags[token] = ambig ? 1 : 0;

            const float mx = tv[0];
            float e0 = expf(tv[0] - mx);
            float e1 = expf(tv[1] - mx);
            float e2 = expf(tv[2] - mx);
            float e3 = expf(tv[3] - mx);
            const float inv = 1.0f / (e0 + e1 + e2 + e3);
            out_vals[(size_t)token * 4 + 0] = e0 * inv;
            out_vals[(size_t)token * 4 + 1] = e1 * inv;
            out_vals[(size_t)token * 4 + 2] = e2 * inv;
            out_vals[(size_t)token * 4 + 3] = e3 * inv;
            out_idx[(size_t)token * 4 + 0] = (float)ti[0];
            out_idx[(size_t)token * 4 + 1] = (float)ti[1];
            out_idx[(size_t)token * 4 + 2] = (float)ti[2];
            out_idx[(size_t)token * 4 + 3] = (float)ti[3];
        }
    }
}

// ---------------- Refinement kernel ----------------
// One CTA (256 threads) per token; early-exit on clear flag.
// thread t -> expert e = t/2, half h = t%2 of the H dimension.
// Compensated accumulation: TwoProd (fmaf) + Neumaier TwoSum.
__global__ __launch_bounds__(256, 8)
void refine_kernel(const float* __restrict__ X,
                   const float* __restrict__ W,
                   const float* __restrict__ bias,
                   float* __restrict__ out_vals,
                   float* __restrict__ out_idx,
                   int T, int H)
{
    const int token = blockIdx.x;
    if (token >= T) return;
    if (!g_flags[token]) return;

    __shared__ double s_partial[256];
    __shared__ double s_logit[128];

    const int e = threadIdx.x >> 1;
    const int h = threadIdx.x & 1;
    const int half = H >> 1;

    const float* xr = X + (size_t)token * H + (size_t)h * half;
    const float* wr = W + (size_t)e * H + (size_t)h * half;

    // two independent double-float accumulators to hide dependency latency
    float hi0 = 0.f, lo0 = 0.f, hi1 = 0.f, lo1 = 0.f;
    for (int i = 0; i < half; i += 2) {
        {   // accumulator 0
            float a = xr[i], b = wr[i];
            float p  = a * b;
            float pe = fmaf(a, b, -p);
            float s  = hi0 + p;
            float z  = s - hi0;
            float er = (hi0 - (s - z)) + (p - z);
            hi0 = s;
            lo0 += er + pe;
        }
        {   // accumulator 1
            float a = xr[i + 1], b = wr[i + 1];
            float p  = a * b;
            float pe = fmaf(a, b, -p);
            float s  = hi1 + p;
            float z  = s - hi1;
            float er = (hi1 - (s - z)) + (p - z);
            hi1 = s;
            lo1 += er + pe;
        }
    }
    s_partial[threadIdx.x] = ((double)hi0 + (double)lo0) +
                             ((double)hi1 + (double)lo1);
    __syncthreads();

    if (h == 0)
        s_logit[e] = s_partial[2 * e] + s_partial[2 * e + 1] + (double)bias[e];
    __syncthreads();

    if (threadIdx.x == 0) {
        double tv[4] = {-1e300, -1e300, -1e300, -1e300};
        int    ti[4] = {0, 0, 0, 0};
        for (int k = 0; k < 128; k++) {
            double val = s_logit[k];
            if (val > tv[3]) {
                tv[3] = val; ti[3] = k;
                #pragma unroll
                for (int s = 3; s > 0; s--) {
                    if (tv[s] > tv[s - 1]) {
                        double fv = tv[s]; tv[s] = tv[s - 1]; tv[s - 1] = fv;
                        int    fi = ti[s]; ti[s] = ti[s - 1]; ti[s - 1] = fi;
                    }
                }
            }
        }
        float v0 = (float)tv[0], v1 = (float)tv[1],
              v2 = (float)tv[2], v3 = (float)tv[3];
        float mx = v0;
        float e0 = expf(v0 - mx);
        float e1 = expf(v1 - mx);
        float e2 = expf(v2 - mx);
        float e3 = expf(v3 - mx);
        float inv = 1.0f / (e0 + e1 + e2 + e3);
        out_vals[(size_t)token * 4 + 0] = e0 * inv;
        out_vals[(size_t)token * 4 + 1] = e1 * inv;
        out_vals[(size_t)token * 4 + 2] = e2 * inv;
        out_vals[(size_t)token * 4 + 3] = e3 * inv;
        out_idx[(size_t)token * 4 + 0] = (float)ti[0];
        out_idx[(size_t)token * 4 + 1] = (float)ti[1];
        out_idx[(size_t)token * 4 + 2] = (float)ti[2];
        out_idx[(size_t)token * 4 + 3] = (float)ti[3];
    }
}

extern "C" void kernel_launch(void* const* d_in, const int* in_sizes, int n_in,
                              void* d_out, int out_size)
{
    const float* X    = (const float*)d_in[0];
    const float* W    = (const float*)d_in[1];
    const float* bias = (const float*)d_in[2];

    const int E = in_sizes[2];          // 128
    const int H = in_sizes[1] / E;      // 2880
    const int T = in_sizes[0] / H;      // 16384

    float* out        = (float*)d_out;
    float* out_vals   = out;                   // [T,4]
    float* out_idx    = out + (size_t)T * 4;   // [T,4]
    float* out_logits = out + (size_t)T * 8;   // [T,E]

    const size_t smemBytes = (size_t)BM * LPAD * sizeof(float); // 66048 B
    cudaFuncSetAttribute(router_topk_kernel,
                         cudaFuncAttributeMaxDynamicSharedMemorySize,
                         (int)smemBytes);

    dim3 grid((T + BM - 1) / BM);
    router_topk_kernel<<<grid, NTHREADS, smemBytes>>>(
        X, W, bias, out_vals, out_idx, out_logits, T, H);

    refine_kernel<<<T, 256>>>(X, W, bias, out_vals, out_idx, T, H);
}

// round 3
// speedup vs baseline: 3.4533x; 3.4533x over previous
#include <cuda_runtime.h>
#include <cuda_bf16.h>
#include <math.h>

// X [T=16384, H=2880] f32; W [E=128, H=2880] f32; bias [E=128] f32
// d_out f32: [0,T*4) softmax vals | [T*4,T*8) indices | [T*8,..) logits [T,E]
//
// Kernel A: zero worklist counter.
// Kernel B: bf16 split-precision (hi+lo, 3-MMA) tensor-core GEMM, BM=128 x
//           BN=128 x BK=32, 8 warps; fused bias/logits/top-5/ambiguity worklist.
// Kernel C: exact (compensated) recompute of worklist tokens; small fixed grid.

#define BM 128
#define BN 128
#define BK 32
#define NTHREADS 256
#define LPAD 129
#define ASTRIDE 20            // u32 row stride for packed bf16 smem tiles (conflict-free)
#define TILE_U32 (128 * ASTRIDE)       // one matrix (hi or lo): 2560 u32
#define STAGE_U32 (4 * TILE_U32)       // Ah,Al,Bh,Bl: 10240 u32 = 40960 B
#define SMEM_BYTES (2 * STAGE_U32 * 4) // double buffered: 81920 B
#define AMBIG_EPS 3e-4f

__device__ int g_count;
__device__ int g_list[65536];

extern __shared__ unsigned int smem_u32[];

__device__ __forceinline__ unsigned int bf16x2_bits(float a, float b) {
    __nv_bfloat162 t = __floats2bfloat162_rn(a, b);   // t.x=a (low), t.y=b (high)
    return *reinterpret_cast<unsigned int*>(&t);
}

__device__ __forceinline__ void cvt_pair(float x0, float x1,
                                         unsigned int& hi, unsigned int& lo) {
    float h0 = __bfloat162float(__float2bfloat16_rn(x0));
    float h1 = __bfloat162float(__float2bfloat16_rn(x1));
    hi = bf16x2_bits(h0, h1);
    lo = bf16x2_bits(x0 - h0, x1 - h1);
}

__device__ __forceinline__ void mma16816(float* c, const unsigned int* a,
                                         unsigned int b0, unsigned int b1) {
    asm volatile(
        "mma.sync.aligned.m16n8k16.row.col.f32.bf16.bf16.f32 "
        "{%0,%1,%2,%3}, {%4,%5,%6,%7}, {%8,%9}, {%0,%1,%2,%3};"
        : "+f"(c[0]), "+f"(c[1]), "+f"(c[2]), "+f"(c[3])
        : "r"(a[0]), "r"(a[1]), "r"(a[2]), "r"(a[3]), "r"(b0), "r"(b1));
}

__global__ void zero_kernel() {
    if (threadIdx.x == 0) g_count = 0;
}

__global__ __launch_bounds__(NTHREADS, 1)
void gemm_kernel(const float* __restrict__ X,
                 const float* __restrict__ W,
                 const float* __restrict__ bias,
                 float* __restrict__ out_vals,
                 float* __restrict__ out_idx,
                 float* __restrict__ out_logits,
                 int T, int H)
{
    const int tid  = threadIdx.x;
    const int warp = tid >> 5;
    const int lane = tid & 31;
    const int g    = lane >> 2;     // 0..7
    const int tg   = lane & 3;      // 0..3
    const int wm   = warp >> 1;     // 0..3 -> rows 32*wm
    const int wn   = warp & 1;      // 0..1 -> cols 64*wn
    const int rowBase = blockIdx.x * BM;

    // cooperative f32 load mapping: k4 = tid&7 (float4 col), rows tid>>3 + 32*j
    const int k4 = tid & 7;
    const int r0 = tid >> 3;

    const int numTiles = H / BK;   // 90

    float acc[2][8][4];
    #pragma unroll
    for (int mt = 0; mt < 2; mt++)
        #pragma unroll
        for (int nt = 0; nt < 8; nt++)
            #pragma unroll
            for (int i = 0; i < 4; i++) acc[mt][nt][i] = 0.0f;

    const float* xp[4];
    const float* wp[4];
    #pragma unroll
    for (int j = 0; j < 4; j++) {
        xp[j] = X + (size_t)(rowBase + r0 + 32 * j) * H + k4 * 4;
        wp[j] = W + (size_t)(r0 + 32 * j) * H + k4 * 4;
    }

    float4 ax[4], bx[4];
    #pragma unroll
    for (int j = 0; j < 4; j++) {
        ax[j] = *(const float4*)(xp[j]);
        bx[j] = *(const float4*)(wp[j]);
    }

    // convert + store into buffer 0
    {
        unsigned int* Ah = smem_u32;
        unsigned int* Al = Ah + TILE_U32;
        unsigned int* Bh = Al + TILE_U32;
        unsigned int* Bl = Bh + TILE_U32;
        #pragma unroll
        for (int j = 0; j < 4; j++) {
            const int row = r0 + 32 * j;
            const int kk  = k4 * 2;
            unsigned int h01, l01, h23, l23;
            cvt_pair(ax[j].x, ax[j].y, h01, l01);
            cvt_pair(ax[j].z, ax[j].w, h23, l23);
            Ah[row * ASTRIDE + kk]     = h01;
            Ah[row * ASTRIDE + kk + 1] = h23;
            Al[row * ASTRIDE + kk]     = l01;
            Al[row * ASTRIDE + kk + 1] = l23;
            cvt_pair(bx[j].x, bx[j].y, h01, l01);
            cvt_pair(bx[j].z, bx[j].w, h23, l23);
            Bh[row * ASTRIDE + kk]     = h01;
            Bh[row * ASTRIDE + kk + 1] = h23;
            Bl[row * ASTRIDE + kk]     = l01;
            Bl[row * ASTRIDE + kk + 1] = l23;
        }
    }
    __syncthreads();

    for (int t = 0; t < numTiles; t++) {
        if (t + 1 < numTiles) {
            const int koff = (t + 1) * BK;
            #pragma unroll
            for (int j = 0; j < 4; j++) {
                ax[j] = *(const float4*)(xp[j] + koff);
                bx[j] = *(const float4*)(wp[j] + koff);
            }
        }

        const unsigned int* base = smem_u32 + (t & 1) * STAGE_U32;
        const unsigned int* Ah = base;
        const unsigned int* Al = Ah + TILE_U32;
        const unsigned int* Bh = Al + TILE_U32;
        const unsigned int* Bl = Bh + TILE_U32;

        #pragma unroll
        for (int s = 0; s < 2; s++) {
            const int kb = s * 8;
            unsigned int ah[2][4], al[2][4];
            #pragma unroll
            for (int mt = 0; mt < 2; mt++) {
                const int rb = 32 * wm + 16 * mt;
                ah[mt][0] = Ah[(rb + g) * ASTRIDE + kb + tg];
                ah[mt][1] = Ah[(rb + g + 8) * ASTRIDE + kb + tg];
                ah[mt][2] = Ah[(rb + g) * ASTRIDE + kb + tg + 4];
                ah[mt][3] = Ah[(rb + g + 8) * ASTRIDE + kb + tg + 4];
                al[mt][0] = Al[(rb + g) * ASTRIDE + kb + tg];
                al[mt][1] = Al[(rb + g + 8) * ASTRIDE + kb + tg];
                al[mt][2] = Al[(rb + g) * ASTRIDE + kb + tg + 4];
                al[mt][3] = Al[(rb + g + 8) * ASTRIDE + kb + tg + 4];
            }
            #pragma unroll
            for (int nt = 0; nt < 8; nt++) {
                const int cb = 64 * wn + 8 * nt;
                unsigned int bh0 = Bh[(cb + g) * ASTRIDE + kb + tg];
                unsigned int bh1 = Bh[(cb + g) * ASTRIDE + kb + tg + 4];
                unsigned int bl0 = Bl[(cb + g) * ASTRIDE + kb + tg];
                unsigned int bl1 = Bl[(cb + g) * ASTRIDE + kb + tg + 4];
                #pragma unroll
                for (int mt = 0; mt < 2; mt++) {
                    mma16816(acc[mt][nt], ah[mt], bh0, bh1);
                    mma16816(acc[mt][nt], ah[mt], bl0, bl1);
                    mma16816(acc[mt][nt], al[mt], bh0, bh1);
                }
            }
        }

        if (t + 1 < numTiles) {
            unsigned int* nb = smem_u32 + ((t + 1) & 1) * STAGE_U32;
            unsigned int* nAh = nb;
            unsigned int* nAl = nAh + TILE_U32;
            unsigned int* nBh = nAl + TILE_U32;
            unsigned int* nBl = nBh + TILE_U32;
            #pragma unroll
            for (int j = 0; j < 4; j++) {
                const int row = r0 + 32 * j;
                const int kk  = k4 * 2;
                unsigned int h01, l01, h23, l23;
                cvt_pair(ax[j].x, ax[j].y, h01, l01);
                cvt_pair(ax[j].z, ax[j].w, h23, l23);
                nAh[row * ASTRIDE + kk]     = h01;
                nAh[row * ASTRIDE + kk + 1] = h23;
                nAl[row * ASTRIDE + kk]     = l01;
                nAl[row * ASTRIDE + kk + 1] = l23;
                cvt_pair(bx[j].x, bx[j].y, h01, l01);
                cvt_pair(bx[j].z, bx[j].w, h23, l23);
                nBh[row * ASTRIDE + kk]     = h01;
                nBh[row * ASTRIDE + kk + 1] = h23;
                nBl[row * ASTRIDE + kk]     = l01;
                nBl[row * ASTRIDE + kk + 1] = l23;
            }
            __syncthreads();
        }
    }

    // ---------------- Epilogue ----------------
    __syncthreads();              // all smem tile reads done; reuse as Ls
    float* Ls = (float*)smem_u32; // [BM][LPAD]

    #pragma unroll
    for (int mt = 0; mt < 2; mt++) {
        const int rb = 32 * wm + 16 * mt;
        #pragma unroll
        for (int nt = 0; nt < 8; nt++) {
            const int cb = 64 * wn + 8 * nt + 2 * tg;
            const float b0 = bias[cb];
            const float b1 = bias[cb + 1];
            Ls[(rb + g) * LPAD + cb]         = acc[mt][nt][0] + b0;
            Ls[(rb + g) * LPAD + cb + 1]     = acc[mt][nt][1] + b1;
            Ls[(rb + g + 8) * LPAD + cb]     = acc[mt][nt][2] + b0;
            Ls[(rb + g + 8) * LPAD + cb + 1] = acc[mt][nt][3] + b1;
        }
    }
    __syncthreads();

    // logits to gmem, coalesced float4
    #pragma unroll
    for (int i = 0; i < 16; i++) {
        const int idx = tid + NTHREADS * i;        // 0..4095 float4 ids
        const int row = idx >> 5;                  // 32 float4 per row
        const int c4  = idx & 31;
        float4 v;
        v.x = Ls[row * LPAD + c4 * 4 + 0];
        v.y = Ls[row * LPAD + c4 * 4 + 1];
        v.z = Ls[row * LPAD + c4 * 4 + 2];
        v.w = Ls[row * LPAD + c4 * 4 + 3];
        *(float4*)&out_logits[(size_t)(rowBase + row) * BN + c4 * 4] = v;
    }

    // top-5 + softmax + ambiguity worklist
    if (tid < BM) {
        const int token = rowBase + tid;
        const float* row = &Ls[tid * LPAD];
        float tv[5] = {-1e30f, -1e30f, -1e30f, -1e30f, -1e30f};
        int   ti[5] = {0, 0, 0, 0, 0};
        for (int e = 0; e < BN; e++) {
            float val = row[e];
            if (val > tv[4]) {
                tv[4] = val; ti[4] = e;
                #pragma unroll
                for (int s = 4; s > 0; s--) {
                    if (tv[s] > tv[s - 1]) {
                        float fv = tv[s]; tv[s] = tv[s - 1]; tv[s - 1] = fv;
                        int   fi = ti[s]; ti[s] = ti[s - 1]; ti[s - 1] = fi;
                    }
                }
            }
        }
        bool ambig = (tv[0] - tv[1] < AMBIG_EPS) |
                     (tv[1] - tv[2] < AMBIG_EPS) |
                     (tv[2] - tv[3] < AMBIG_EPS) |
                     (tv[3] - tv[4] < AMBIG_EPS);
        if (ambig) {
            int p = atomicAdd(&g_count, 1);
            g_list[p] = token;
        }
        const float mx = tv[0];
        float e0 = expf(tv[0] - mx);
        float e1 = expf(tv[1] - mx);
        float e2 = expf(tv[2] - mx);
        float e3 = expf(tv[3] - mx);
        const float inv = 1.0f / (e0 + e1 + e2 + e3);
        out_vals[(size_t)token * 4 + 0] = e0 * inv;
        out_vals[(size_t)token * 4 + 1] = e1 * inv;
        out_vals[(size_t)token * 4 + 2] = e2 * inv;
        out_vals[(size_t)token * 4 + 3] = e3 * inv;
        out_idx[(size_t)token * 4 + 0] = (float)ti[0];
        out_idx[(size_t)token * 4 + 1] = (float)ti[1];
        out_idx[(size_t)token * 4 + 2] = (float)ti[2];
        out_idx[(size_t)token * 4 + 3] = (float)ti[3];
    }
}

// ---------------- Refinement over compacted worklist ----------------
// thread t -> expert e = t/2, half h = t%2 (1440 floats = 360 float4).
// 4 independent compensated (TwoProd+TwoSum) accumulators, combined in fp64.
__global__ __launch_bounds__(256, 4)
void refine_kernel(const float* __restrict__ X,
                   const float* __restrict__ W,
                   const float* __restrict__ bias,
                   float* __restrict__ out_vals,
                   float* __restrict__ out_idx,
                   int T, int H)
{
    const int cnt = *(volatile int*)&g_count;
    __shared__ double s_partial[256];
    __shared__ double s_logit[128];

    const int e = threadIdx.x >> 1;
    const int h = threadIdx.x & 1;
    const int half = H >> 1;           // 1440
    const int nq = half >> 2;          // 360

    for (int it = blockIdx.x; it < cnt; it += gridDim.x) {
        const int token = g_list[it];
        const float4* xr = (const float4*)(X + (size_t)token * H + (size_t)h * half);
        const float4* wr = (const float4*)(W + (size_t)e * H + (size_t)h * half);

        float s[4] = {0.f, 0.f, 0.f, 0.f};
        float c[4] = {0.f, 0.f, 0.f, 0.f};
        for (int i = 0; i < nq; i++) {
            float4 xv = xr[i];
            float4 wv = wr[i];
            float a4[4] = {xv.x, xv.y, xv.z, xv.w};
            float b4[4] = {wv.x, wv.y, wv.z, wv.w};
            #pragma unroll
            for (int l = 0; l < 4; l++) {
                float p  = a4[l] * b4[l];
                float pe = fmaf(a4[l], b4[l], -p);
                float t2 = s[l] + p;
                float z  = t2 - s[l];
                float er = (s[l] - (t2 - z)) + (p - z);
                s[l] = t2;
                c[l] += er + pe;
            }
        }
        double tot = 0.0;
        #pragma unroll
        for (int l = 0; l < 4; l++) tot += (double)s[l] + (double)c[l];
        s_partial[threadIdx.x] = tot;
        __syncthreads();

        if (h == 0)
            s_logit[e] = s_partial[2 * e] + s_partial[2 * e + 1] + (double)bias[e];
        __syncthreads();

        if (threadIdx.x == 0) {
            double tv[4] = {-1e300, -1e300, -1e300, -1e300};
            int    ti[4] = {0, 0, 0, 0};
            for (int k = 0; k < 128; k++) {
                double val = s_logit[k];
                if (val > tv[3]) {
                    tv[3] = val; ti[3] = k;
                    #pragma unroll
                    for (int s2 = 3; s2 > 0; s2--) {
                        if (tv[s2] > tv[s2 - 1]) {
                            double fv = tv[s2]; tv[s2] = tv[s2 - 1]; tv[s2 - 1] = fv;
                            int    fi = ti[s2]; ti[s2] = ti[s2 - 1]; ti[s2 - 1] = fi;
                        }
                    }
                }
            }
            float v0 = (float)tv[0], v1 = (float)tv[1],
                  v2 = (float)tv[2], v3 = (float)tv[3];
            float e0 = expf(v0 - v0);
            float e1 = expf(v1 - v0);
            float e2 = expf(v2 - v0);
            float e3 = expf(v3 - v0);
            float inv = 1.0f / (e0 + e1 + e2 + e3);
            out_vals[(size_t)token * 4 + 0] = e0 * inv;
            out_vals[(size_t)token * 4 + 1] = e1 * inv;
            out_vals[(size_t)token * 4 + 2] = e2 * inv;
            out_vals[(size_t)token * 4 + 3] = e3 * inv;
            out_idx[(size_t)token * 4 + 0] = (float)ti[0];
            out_idx[(size_t)token * 4 + 1] = (float)ti[1];
            out_idx[(size_t)token * 4 + 2] = (float)ti[2];
            out_idx[(size_t)token * 4 + 3] = (float)ti[3];
        }
        __syncthreads();
    }
}

extern "C" void kernel_launch(void* const* d_in, const int* in_sizes, int n_in,
                              void* d_out, int out_size)
{
    const float* X    = (const float*)d_in[0];
    const float* W    = (const float*)d_in[1];
    const float* bias = (const float*)d_in[2];

    const int E = in_sizes[2];          // 128
    const int H = in_sizes[1] / E;      // 2880
    const int T = in_sizes[0] / H;      // 16384

    float* out        = (float*)d_out;
    float* out_vals   = out;
    float* out_idx    = out + (size_t)T * 4;
    float* out_logits = out + (size_t)T * 8;

    cudaFuncSetAttribute(gemm_kernel,
                         cudaFuncAttributeMaxDynamicSharedMemorySize,
                         SMEM_BYTES);

    zero_kernel<<<1, 32>>>();
    gemm_kernel<<<(T + BM - 1) / BM, NTHREADS, SMEM_BYTES>>>(
        X, W, bias, out_vals, out_idx, out_logits, T, H);
    refine_kernel<<<256, 256>>>(X, W, bias, out_vals, out_idx, T, H);
}